// round 2
// baseline (speedup 1.0000x reference)
#include <cuda_runtime.h>
#include <math.h>

#define BB 32
#define NN 1024
#define KK 64
#define DD 1536

typedef unsigned long long u64;

// ---------------- device scratch (no allocations allowed) ----------------
__device__ float g_cnorm[KK * DD];                    // normalized centers
__device__ int   g_labels[BB * NN];                   // argmax labels
__device__ float g_vlad[(size_t)BB * KK * DD];        // intra-normalized vlad
__device__ float g_kssq[BB * KK];                     // per-(b,k) ||t||^2
__device__ float g_binv[BB];                          // per-b global inverse norm

union F2U { float2 f; u64 u; };

// Packed fp32x2 FMA (Blackwell sm_100+): 2 FMAs per issue slot.
// Guarded fallback keeps the TU compilable on any arch.
__device__ __forceinline__ u64 ffma2(u64 a, u64 b, u64 c) {
#if defined(__CUDA_ARCH__) && (__CUDA_ARCH__ >= 1000)
    u64 d;
    asm("fma.rn.f32x2 %0, %1, %2, %3;" : "=l"(d) : "l"(a), "l"(b), "l"(c));
    return d;
#else
    F2U fa, fb, fc, fd;
    fa.u = a; fb.u = b; fc.u = c;
    fd.f.x = fmaf(fa.f.x, fb.f.x, fc.f.x);
    fd.f.y = fmaf(fa.f.y, fb.f.y, fc.f.y);
    return fd.u;
#endif
}

// -------------------------------------------------------------------------
// K1: normalize cluster centers (c / max(||c||, eps))
// -------------------------------------------------------------------------
__global__ void k_centers(const float* __restrict__ cen) {
    int k = blockIdx.x, tid = threadIdx.x;
    float s = 0.f;
    for (int d = tid; d < DD; d += 256) {
        float v = cen[k * DD + d];
        s = fmaf(v, v, s);
    }
    __shared__ float red[9];
    #pragma unroll
    for (int o = 16; o > 0; o >>= 1) s += __shfl_xor_sync(0xffffffffu, s, o);
    if ((tid & 31) == 0) red[tid >> 5] = s;
    __syncthreads();
    if (tid < 32) {
        float t = (tid < 8) ? red[tid] : 0.f;
        #pragma unroll
        for (int o = 4; o > 0; o >>= 1) t += __shfl_xor_sync(0xffffffffu, t, o);
        if (tid == 0) red[8] = 1.0f / fmaxf(sqrtf(t), 1e-12f);
    }
    __syncthreads();
    float inv = red[8];
    for (int d = tid; d < DD; d += 256)
        g_cnorm[k * DD + d] = cen[k * DD + d] * inv;
}

// -------------------------------------------------------------------------
// K2: sims GEMM + argmax.  argmax_k <desc, cnorm_k> is invariant to the
// descriptor's (positive) scale, so raw descriptors are used here — no
// per-row normalization needed for the assignment.
// 256 rows/block x all 64 centers, 8x8 register tile, f32x2 packed math.
// -------------------------------------------------------------------------
__global__ __launch_bounds__(256, 1) void k_assign(const float* __restrict__ descs) {
    __shared__ __align__(16) u64 As[8][256];   // [d-pair][row]   16 KB
    __shared__ __align__(16) u64 Bs[8][64];    // [d-pair][k]      4 KB
    __shared__ float pv[256][8];               //                  8 KB
    __shared__ int   pk[256][8];               //                  8 KB

    int tid  = threadIdx.x;
    int tcol = tid & 7;          // 8 center-tiles of 8
    int trow = tid >> 3;         // 32 row-tiles of 8
    size_t row0 = (size_t)blockIdx.x * 256;

    u64 acc[8][8];
    #pragma unroll
    for (int i = 0; i < 8; i++)
        #pragma unroll
        for (int j = 0; j < 8; j++) acc[i][j] = 0ull;   // == (0.f, 0.f)

    for (int d0 = 0; d0 < DD; d0 += 16) {
        // stage 256x16 descriptor chunk
        #pragma unroll
        for (int i = 0; i < 4; i++) {
            int t = tid + i * 256;
            int r = t >> 2, seg = t & 3;
            const float4 v = *(const float4*)(descs + (row0 + r) * DD + d0 + seg * 4);
            F2U lo, hi;
            lo.f = make_float2(v.x, v.y);
            hi.f = make_float2(v.z, v.w);
            As[seg * 2][r]     = lo.u;
            As[seg * 2 + 1][r] = hi.u;
        }
        // stage 64x16 center chunk
        {
            int kk = tid >> 2, seg = tid & 3;
            const float4 v = *(const float4*)(g_cnorm + kk * DD + d0 + seg * 4);
            F2U lo, hi;
            lo.f = make_float2(v.x, v.y);
            hi.f = make_float2(v.z, v.w);
            Bs[seg * 2][kk]     = lo.u;
            Bs[seg * 2 + 1][kk] = hi.u;
        }
        __syncthreads();
        #pragma unroll
        for (int p = 0; p < 8; p++) {
            u64 b[8];
            const ulonglong2* bp = (const ulonglong2*)&Bs[p][tcol * 8];
            #pragma unroll
            for (int j = 0; j < 4; j++) { ulonglong2 t = bp[j]; b[2*j] = t.x; b[2*j+1] = t.y; }
            const ulonglong2* ap = (const ulonglong2*)&As[p][trow * 8];
            #pragma unroll
            for (int i2 = 0; i2 < 4; i2++) {        // stream A two rows at a time
                ulonglong2 t = ap[i2];
                #pragma unroll
                for (int j = 0; j < 8; j++) {
                    acc[2*i2][j]   = ffma2(t.x, b[j], acc[2*i2][j]);
                    acc[2*i2+1][j] = ffma2(t.y, b[j], acc[2*i2+1][j]);
                }
            }
        }
        __syncthreads();
    }

    // per-thread argmax over its 8 centers, for each of its 8 rows
    #pragma unroll
    for (int i = 0; i < 8; i++) {
        float best = -3.4e38f; int bk = 0;
        #pragma unroll
        for (int j = 0; j < 8; j++) {
            F2U t; t.u = acc[i][j];
            float f = t.f.x + t.f.y;
            if (f > best) { best = f; bk = tcol * 8 + j; }
        }
        pv[trow * 8 + i][tcol] = best;
        pk[trow * 8 + i][tcol] = bk;
    }
    __syncthreads();
    {
        // combine 8 partials per row; c ascending keeps lowest-k on ties
        float best = -3.4e38f; int bk = 0;
        #pragma unroll
        for (int c = 0; c < 8; c++) {
            float f = pv[tid][c];
            if (f > best) { best = f; bk = pk[tid][c]; }
        }
        g_labels[row0 + tid] = bk;
    }
}

// -------------------------------------------------------------------------
// block-wide sum with broadcast (256 threads)
// -------------------------------------------------------------------------
__device__ __forceinline__ float blockSum256(float v, float* red) {
    #pragma unroll
    for (int o = 16; o > 0; o >>= 1) v += __shfl_xor_sync(0xffffffffu, v, o);
    if ((threadIdx.x & 31) == 0) red[threadIdx.x >> 5] = v;
    __syncthreads();
    if (threadIdx.x < 32) {
        float t = (threadIdx.x < 8) ? red[threadIdx.x] : 0.f;
        #pragma unroll
        for (int o = 4; o > 0; o >>= 1) t += __shfl_xor_sync(0xffffffffu, t, o);
        if (threadIdx.x == 0) red[8] = t;
    }
    __syncthreads();
    return red[8];
}

// -------------------------------------------------------------------------
// K3: per-(b,k) gather + normalized sum + residual + intra-normalize.
// Labels preloaded to SMEM -> uniform branch; deterministic ascending-n sum.
// Each thread owns 6 of the 1536 dims (3 float2, fully coalesced).
// -------------------------------------------------------------------------
__global__ void k_agg(const float* __restrict__ descs, const float* __restrict__ cen) {
    int k = blockIdx.x, b = blockIdx.y, tid = threadIdx.x;
    __shared__ int   slab[NN];
    __shared__ float red[9];
    for (int n = tid; n < NN; n += 256) slab[n] = g_labels[b * NN + n];
    __syncthreads();

    const float2* base = (const float2*)descs + (size_t)b * NN * (DD / 2);
    float2 a0 = make_float2(0.f, 0.f), a1 = a0, a2 = a0;
    int cnt = 0;

    for (int n = 0; n < NN; n++) {
        if (slab[n] != k) continue;          // uniform across block
        cnt++;
        const float2* rp = base + (size_t)n * (DD / 2);
        float2 v0 = rp[tid], v1 = rp[tid + 256], v2 = rp[tid + 512];
        float s = v0.x * v0.x + v0.y * v0.y
                + v1.x * v1.x + v1.y * v1.y
                + v2.x * v2.x + v2.y * v2.y;
        float tot = blockSum256(s, red);
        float inv = 1.0f / fmaxf(sqrtf(tot), 1e-12f);
        a0.x = fmaf(v0.x, inv, a0.x); a0.y = fmaf(v0.y, inv, a0.y);
        a1.x = fmaf(v1.x, inv, a1.x); a1.y = fmaf(v1.y, inv, a1.y);
        a2.x = fmaf(v2.x, inv, a2.x); a2.y = fmaf(v2.y, inv, a2.y);
    }

    // un_vlad = sum - count * raw_center
    const float2* cp = (const float2*)cen + (size_t)k * (DD / 2);
    float fc = (float)cnt;
    float2 c0 = cp[tid], c1 = cp[tid + 256], c2 = cp[tid + 512];
    float2 u0, u1, u2;
    u0.x = a0.x - fc * c0.x; u0.y = a0.y - fc * c0.y;
    u1.x = a1.x - fc * c1.x; u1.y = a1.y - fc * c1.y;
    u2.x = a2.x - fc * c2.x; u2.y = a2.y - fc * c2.y;

    float s = u0.x * u0.x + u0.y * u0.y
            + u1.x * u1.x + u1.y * u1.y
            + u2.x * u2.x + u2.y * u2.y;
    float tot = blockSum256(s, red);
    float inv = 1.0f / fmaxf(sqrtf(tot), 1e-12f);

    float2* vp = (float2*)g_vlad + ((size_t)b * KK + k) * (DD / 2);
    float2 o0, o1, o2;
    o0.x = u0.x * inv; o0.y = u0.y * inv;
    o1.x = u1.x * inv; o1.y = u1.y * inv;
    o2.x = u2.x * inv; o2.y = u2.y * inv;
    vp[tid] = o0; vp[tid + 256] = o1; vp[tid + 512] = o2;

    if (tid == 0) g_kssq[b * KK + k] = tot * inv * inv;   // ||t_k||^2 (0 if empty)
}

// -------------------------------------------------------------------------
// K4: fold per-(b,k) norms into per-b global inverse norm (deterministic tree)
// -------------------------------------------------------------------------
__global__ void k_bnorm() {
    int b = blockIdx.x, tid = threadIdx.x;   // 64 threads
    float v = g_kssq[b * KK + tid];
    #pragma unroll
    for (int o = 16; o > 0; o >>= 1) v += __shfl_xor_sync(0xffffffffu, v, o);
    __shared__ float sh[2];
    if ((tid & 31) == 0) sh[tid >> 5] = v;
    __syncthreads();
    if (tid == 0) g_binv[b] = 1.0f / fmaxf(sqrtf(sh[0] + sh[1]), 1e-12f);
}

// -------------------------------------------------------------------------
// K5: global scale, vectorized write of output
// -------------------------------------------------------------------------
__global__ void k_scale(float* __restrict__ out) {
    size_t i = (size_t)blockIdx.x * 256 + threadIdx.x;   // float4 index
    int b = (int)(i / (KK * DD / 4));
    float inv = g_binv[b];
    float4 v = ((const float4*)g_vlad)[i];
    v.x *= inv; v.y *= inv; v.z *= inv; v.w *= inv;
    ((float4*)out)[i] = v;
}

// -------------------------------------------------------------------------
extern "C" void kernel_launch(void* const* d_in, const int* in_sizes, int n_in,
                              void* d_out, int out_size) {
    const float* descs = (const float*)d_in[0];   // [B,N,D] fp32
    const float* cen   = (const float*)d_in[1];   // [K,D]   fp32
    float* out = (float*)d_out;                   // [B, K*D] fp32

    k_centers<<<KK, 256>>>(cen);
    k_assign<<<(BB * NN) / 256, 256>>>(descs);
    dim3 gagg(KK, BB);
    k_agg<<<gagg, 256>>>(descs, cen);
    k_bnorm<<<BB, 64>>>();
    k_scale<<<((size_t)BB * KK * DD / 4) / 256, 256>>>(out);
}